// round 13
// baseline (speedup 1.0000x reference)
#include <cuda_runtime.h>
#include <cuda_bf16.h>
#include <cstdint>

// Problem constants
#define NN      50000
#define EE      800000
#define DIN     128
#define DOUT    128
#define KK      3
#define SUPW    (DOUT * KK)   // 384 floats per node
#define BSTRIDE 64            // max edges per col bucket (Binomial max ~35)

// Scratch (static device globals — allocation-free)
__device__ __align__(16) float  g_sup[(size_t)NN * SUPW];     // 76.8 MB
__device__ int                  g_cnt[NN];                    // per-col counts
__device__ __align__(16) float4 g_meta[(size_t)NN * BSTRIDE]; // 51.2 MB

// ---------------------------------------------------------------------------
// Kernel 0: out[n][j] = bias[j]
// ---------------------------------------------------------------------------
__global__ void bias_init_kernel(const float* __restrict__ bias,
                                 float* __restrict__ out, int n) {
    int i = blockIdx.x * blockDim.x + threadIdx.x;
    int total = n * (DOUT / 4);
    if (i < total) {
        const float4* b4 = reinterpret_cast<const float4*>(bias);
        reinterpret_cast<float4*>(out)[i] = b4[i & (DOUT / 4 - 1)];
    }
}

// ---------------------------------------------------------------------------
// Kernel 0b: zero per-col counters (must run every launch — graph replay)
// ---------------------------------------------------------------------------
__global__ void zero_cnt_kernel(int n) {
    int i = blockIdx.x * blockDim.x + threadIdx.x;
    if (i < n) g_cnt[i] = 0;
}

// ---------------------------------------------------------------------------
// Kernel 0c: bucket fill — per edge, append {row, t0, t1, t2} to col bucket.
// edge_idx is int32 [2,E] (JAX x64-disabled coerces the requested int64).
// ---------------------------------------------------------------------------
__global__ __launch_bounds__(256)
void fill_kernel(const float* __restrict__ TT,
                 const int* __restrict__ eidx, int n_edges) {
    int e = blockIdx.x * blockDim.x + threadIdx.x;
    if (e >= n_edges) return;
    int row = eidx[e];
    int col = eidx[n_edges + e];
    float t0 = TT[e * 3 + 0];
    float t1 = TT[e * 3 + 1];
    float t2 = TT[e * 3 + 2];
    int pos = atomicAdd(&g_cnt[col], 1);
    if (pos < BSTRIDE)
        g_meta[(size_t)col * BSTRIDE + pos] =
            make_float4(__int_as_float(row), t0, t1, t2);
}

// ---------------------------------------------------------------------------
// Kernel 1: tf32 tensor-core GEMM.  g_sup[:, kern*128 + n] = x @ W[:,:,kern]
// ---------------------------------------------------------------------------
#define GM 128
#define GN 128
#define BK 32
#define SSTR 136   // smem row stride in words

__device__ __forceinline__ uint32_t f32_to_tf32(float f) {
    uint32_t r;
    asm("cvt.rna.tf32.f32 %0, %1;" : "=r"(r) : "f"(f));
    return r;
}

__device__ __forceinline__ void mma_tf32(float c[4], uint32_t a0, uint32_t a1,
                                         uint32_t a2, uint32_t a3,
                                         uint32_t b0, uint32_t b1) {
    asm volatile(
        "mma.sync.aligned.m16n8k8.row.col.f32.tf32.tf32.f32 "
        "{%0,%1,%2,%3}, {%4,%5,%6,%7}, {%8,%9}, {%0,%1,%2,%3};"
        : "+f"(c[0]), "+f"(c[1]), "+f"(c[2]), "+f"(c[3])
        : "r"(a0), "r"(a1), "r"(a2), "r"(a3), "r"(b0), "r"(b1));
}

__global__ __launch_bounds__(256)
void gemm_tc_kernel(const float* __restrict__ X, const float* __restrict__ W,
                    int n_nodes) {
    __shared__ uint32_t As[BK][SSTR];   // [k][m] tf32 bits
    __shared__ uint32_t Bs[BK][SSTR];   // [k][n] tf32 bits

    const int kern = blockIdx.x;              // 0..2
    const int m0   = blockIdx.y * GM;
    const int tid  = threadIdx.x;
    const int wid  = tid >> 5;
    const int lane = tid & 31;
    const int qrow = lane >> 2;               // 0..7
    const int qcol = lane & 3;                // 0..3

    const int warp_m = (wid & 1) * 64;        // 0 or 64
    const int warp_n = (wid >> 1) * 32;       // 0,32,64,96

    float acc[4][4][4];                       // [mi][ni][frag]
    #pragma unroll
    for (int mi = 0; mi < 4; ++mi)
        #pragma unroll
        for (int ni = 0; ni < 4; ++ni)
            #pragma unroll
            for (int f = 0; f < 4; ++f) acc[mi][ni][f] = 0.0f;

    for (int kk = 0; kk < DIN; kk += BK) {
        // --- stage A: 128 rows x 32 cols, float4 loads, tf32-convert once ---
        #pragma unroll
        for (int j = 0; j < 4; ++j) {
            int idx4 = tid * 4 + j;           // 0..1023
            int row  = idx4 >> 3;             // 0..127
            int c4   = idx4 & 7;              // 0..7
            int gm   = m0 + row;
            float4 v = make_float4(0.f, 0.f, 0.f, 0.f);
            if (gm < n_nodes)
                v = *reinterpret_cast<const float4*>(
                        X + (size_t)gm * DIN + kk + c4 * 4);
            As[c4 * 4 + 0][row] = f32_to_tf32(v.x);
            As[c4 * 4 + 1][row] = f32_to_tf32(v.y);
            As[c4 * 4 + 2][row] = f32_to_tf32(v.z);
            As[c4 * 4 + 3][row] = f32_to_tf32(v.w);
        }
        // --- stage B: Bs[k][n] = W[(kk+k)*384 + n*3 + kern] ---
        #pragma unroll
        for (int r = 0; r < 16; ++r) {
            int idx = tid * 16 + r;           // 0..4095
            int k   = idx >> 7;
            int n   = idx & 127;
            Bs[k][n] = f32_to_tf32(W[(kk + k) * SUPW + n * 3 + kern]);
        }
        __syncthreads();

        // --- 4 k-steps of 8 ---
        #pragma unroll
        for (int ks = 0; ks < 4; ++ks) {
            int k0 = ks * 8;
            uint32_t af[4][4], bf[4][2];
            #pragma unroll
            for (int mi = 0; mi < 4; ++mi) {
                int rb = warp_m + mi * 16;
                af[mi][0] = As[k0 + qcol][rb + qrow];
                af[mi][1] = As[k0 + qcol][rb + 8 + qrow];
                af[mi][2] = As[k0 + 4 + qcol][rb + qrow];
                af[mi][3] = As[k0 + 4 + qcol][rb + 8 + qrow];
            }
            #pragma unroll
            for (int ni = 0; ni < 4; ++ni) {
                int nb = warp_n + ni * 8;
                bf[ni][0] = Bs[k0 + qcol][nb + qrow];
                bf[ni][1] = Bs[k0 + 4 + qcol][nb + qrow];
            }
            #pragma unroll
            for (int mi = 0; mi < 4; ++mi)
                #pragma unroll
                for (int ni = 0; ni < 4; ++ni)
                    mma_tf32(acc[mi][ni], af[mi][0], af[mi][1], af[mi][2],
                             af[mi][3], bf[ni][0], bf[ni][1]);
        }
        __syncthreads();
    }

    // --- epilogue: c0/c1 at (row, 2*qcol), c2/c3 at (row+8, 2*qcol) ---
    #pragma unroll
    for (int mi = 0; mi < 4; ++mi) {
        int gm_lo = m0 + warp_m + mi * 16 + qrow;
        int gm_hi = gm_lo + 8;
        #pragma unroll
        for (int ni = 0; ni < 4; ++ni) {
            int col = kern * DOUT + warp_n + ni * 8 + 2 * qcol;
            if (gm_lo < n_nodes) {
                float2 v = make_float2(acc[mi][ni][0], acc[mi][ni][1]);
                *reinterpret_cast<float2*>(g_sup + (size_t)gm_lo * SUPW + col) = v;
            }
            if (gm_hi < n_nodes) {
                float2 v = make_float2(acc[mi][ni][2], acc[mi][ni][3]);
                *reinterpret_cast<float2*>(g_sup + (size_t)gm_hi * SUPW + col) = v;
            }
        }
    }
}

// ---------------------------------------------------------------------------
// Kernel 2: gather — ONE WARP PER COL. Loads sup[col] once (3 float4/lane),
// then loops over the col's edge bucket with 1-deep meta prefetch:
//   per edge: 12 FMA + red.global.add.v4.f32 into out[row].
// ---------------------------------------------------------------------------
__device__ __forceinline__ void red_add_f32x4(float* dst, float4 m) {
    asm volatile("red.global.add.v4.f32 [%0], {%1, %2, %3, %4};"
                 :: "l"(dst), "f"(m.x), "f"(m.y), "f"(m.z), "f"(m.w)
                 : "memory");
}

__global__ __launch_bounds__(256)
void gather_kernel(float* __restrict__ out, int n_nodes) {
    int col  = blockIdx.x * (blockDim.x >> 5) + (threadIdx.x >> 5);
    if (col >= n_nodes) return;
    int lane = threadIdx.x & 31;

    int cnt = g_cnt[col];
    if (cnt <= 0) return;
    cnt = min(cnt, BSTRIDE);

    // sup[col]: lane's 4 output cols j = 4*lane..4*lane+3 for each of 3 kernels
    const float4* s = reinterpret_cast<const float4*>(g_sup + (size_t)col * SUPW);
    float4 a = s[lane];          // kernel 0
    float4 b = s[32 + lane];     // kernel 1
    float4 c = s[64 + lane];     // kernel 2

    const float4* mp = g_meta + (size_t)col * BSTRIDE;
    float4 meta = mp[0];                       // prefetch edge 0
    for (int i = 0; i < cnt; ++i) {
        float4 nxt = (i + 1 < cnt) ? mp[i + 1] : meta;   // prefetch next
        int   row = __float_as_int(meta.x);
        float t0 = meta.y, t1 = meta.z, t2 = meta.w;
        float4 m;
        m.x = t0 * a.x + t1 * b.x + t2 * c.x;
        m.y = t0 * a.y + t1 * b.y + t2 * c.y;
        m.z = t0 * a.z + t1 * b.z + t2 * c.z;
        m.w = t0 * a.w + t1 * b.w + t2 * c.w;
        red_add_f32x4(out + (size_t)row * DOUT + lane * 4, m);
        meta = nxt;
    }
}

// ---------------------------------------------------------------------------
// Launch
// ---------------------------------------------------------------------------
extern "C" void kernel_launch(void* const* d_in, const int* in_sizes, int n_in,
                              void* d_out, int out_size) {
    const float* x    = (const float*)d_in[0];      // [N,128] f32
    const float* TT   = (const float*)d_in[1];      // [E,3]   f32
    const float* w    = (const float*)d_in[2];      // [128,128,3] f32
    const float* bias = (const float*)d_in[3];      // [128]   f32
    const int*   eidx = (const int*)d_in[4];        // [2,E]   int32
    float*       out  = (float*)d_out;              // [N,128] f32

    int n_nodes = in_sizes[0] / DIN;     // 50000
    int n_edges = in_sizes[1] / KK;      // 800000

    // 0) out = bias
    {
        int total = n_nodes * (DOUT / 4);
        bias_init_kernel<<<(total + 255) / 256, 256>>>(bias, out, n_nodes);
    }
    // 0b) zero bucket counters (every launch — graph replay safe)
    zero_cnt_kernel<<<(n_nodes + 255) / 256, 256>>>(n_nodes);
    // 0c) fill col buckets with packed {row, t0, t1, t2}
    fill_kernel<<<(n_edges + 255) / 256, 256>>>(TT, eidx, n_edges);
    // 1) support_all = x @ W  (tf32 tensor cores)
    {
        dim3 grid(KK, (n_nodes + GM - 1) / GM);
        gemm_tc_kernel<<<grid, 256>>>(x, w, n_nodes);
    }
    // 2) col-grouped gather + RED scatter (one warp per col)
    {
        int warps_per_block = 256 / 32;
        int blocks = (n_nodes + warps_per_block - 1) / warps_per_block;
        gather_kernel<<<blocks, 256>>>(out, n_nodes);
    }
}

// round 14
// speedup vs baseline: 1.0080x; 1.0080x over previous
#include <cuda_runtime.h>
#include <cuda_bf16.h>
#include <cstdint>

// Problem constants
#define NN      50000
#define EE      800000
#define DIN     128
#define DOUT    128
#define KK      3
#define SUPW    (DOUT * KK)   // 384 floats per node
#define BSTRIDE 64            // max edges per col bucket (Binomial max ~35)

// Scratch (static device globals — allocation-free)
__device__ __align__(16) float  g_sup[(size_t)NN * SUPW];     // 76.8 MB
__device__ int                  g_cnt[NN];                    // per-col counts
__device__ __align__(16) float4 g_meta[(size_t)NN * BSTRIDE]; // 51.2 MB

// ---------------------------------------------------------------------------
// Kernel 0: out[n][j] = bias[j]
// ---------------------------------------------------------------------------
__global__ void bias_init_kernel(const float* __restrict__ bias,
                                 float* __restrict__ out, int n) {
    int i = blockIdx.x * blockDim.x + threadIdx.x;
    int total = n * (DOUT / 4);
    if (i < total) {
        const float4* b4 = reinterpret_cast<const float4*>(bias);
        reinterpret_cast<float4*>(out)[i] = b4[i & (DOUT / 4 - 1)];
    }
}

// ---------------------------------------------------------------------------
// Kernel 0b: zero per-col counters (must run every launch — graph replay)
// ---------------------------------------------------------------------------
__global__ void zero_cnt_kernel(int n) {
    int i = blockIdx.x * blockDim.x + threadIdx.x;
    if (i < n) g_cnt[i] = 0;
}

// ---------------------------------------------------------------------------
// Kernel 0c: bucket fill — per edge, append {row, t0, t1, t2} to col bucket.
// edge_idx is int32 [2,E] (JAX x64-disabled coerces the requested int64).
// ---------------------------------------------------------------------------
__global__ __launch_bounds__(256)
void fill_kernel(const float* __restrict__ TT,
                 const int* __restrict__ eidx, int n_edges) {
    int e = blockIdx.x * blockDim.x + threadIdx.x;
    if (e >= n_edges) return;
    int row = eidx[e];
    int col = eidx[n_edges + e];
    float t0 = TT[e * 3 + 0];
    float t1 = TT[e * 3 + 1];
    float t2 = TT[e * 3 + 2];
    int pos = atomicAdd(&g_cnt[col], 1);
    if (pos < BSTRIDE)
        g_meta[(size_t)col * BSTRIDE + pos] =
            make_float4(__int_as_float(row), t0, t1, t2);
}

// ---------------------------------------------------------------------------
// Kernel 1: tf32 tensor-core GEMM.  g_sup[:, kern*128 + n] = x @ W[:,:,kern]
// ---------------------------------------------------------------------------
#define GM 128
#define GN 128
#define BK 32
#define SSTR 136   // smem row stride in words

__device__ __forceinline__ uint32_t f32_to_tf32(float f) {
    uint32_t r;
    asm("cvt.rna.tf32.f32 %0, %1;" : "=r"(r) : "f"(f));
    return r;
}

__device__ __forceinline__ void mma_tf32(float c[4], uint32_t a0, uint32_t a1,
                                         uint32_t a2, uint32_t a3,
                                         uint32_t b0, uint32_t b1) {
    asm volatile(
        "mma.sync.aligned.m16n8k8.row.col.f32.tf32.tf32.f32 "
        "{%0,%1,%2,%3}, {%4,%5,%6,%7}, {%8,%9}, {%0,%1,%2,%3};"
        : "+f"(c[0]), "+f"(c[1]), "+f"(c[2]), "+f"(c[3])
        : "r"(a0), "r"(a1), "r"(a2), "r"(a3), "r"(b0), "r"(b1));
}

__global__ __launch_bounds__(256)
void gemm_tc_kernel(const float* __restrict__ X, const float* __restrict__ W,
                    int n_nodes) {
    __shared__ uint32_t As[BK][SSTR];   // [k][m] tf32 bits
    __shared__ uint32_t Bs[BK][SSTR];   // [k][n] tf32 bits

    const int kern = blockIdx.x;              // 0..2
    const int m0   = blockIdx.y * GM;
    const int tid  = threadIdx.x;
    const int wid  = tid >> 5;
    const int lane = tid & 31;
    const int qrow = lane >> 2;               // 0..7
    const int qcol = lane & 3;                // 0..3

    const int warp_m = (wid & 1) * 64;        // 0 or 64
    const int warp_n = (wid >> 1) * 32;       // 0,32,64,96

    float acc[4][4][4];                       // [mi][ni][frag]
    #pragma unroll
    for (int mi = 0; mi < 4; ++mi)
        #pragma unroll
        for (int ni = 0; ni < 4; ++ni)
            #pragma unroll
            for (int f = 0; f < 4; ++f) acc[mi][ni][f] = 0.0f;

    for (int kk = 0; kk < DIN; kk += BK) {
        // --- stage A: 128 rows x 32 cols, float4 loads, tf32-convert once ---
        #pragma unroll
        for (int j = 0; j < 4; ++j) {
            int idx4 = tid * 4 + j;           // 0..1023
            int row  = idx4 >> 3;             // 0..127
            int c4   = idx4 & 7;              // 0..7
            int gm   = m0 + row;
            float4 v = make_float4(0.f, 0.f, 0.f, 0.f);
            if (gm < n_nodes)
                v = *reinterpret_cast<const float4*>(
                        X + (size_t)gm * DIN + kk + c4 * 4);
            As[c4 * 4 + 0][row] = f32_to_tf32(v.x);
            As[c4 * 4 + 1][row] = f32_to_tf32(v.y);
            As[c4 * 4 + 2][row] = f32_to_tf32(v.z);
            As[c4 * 4 + 3][row] = f32_to_tf32(v.w);
        }
        // --- stage B: Bs[k][n] = W[(kk+k)*384 + n*3 + kern] ---
        #pragma unroll
        for (int r = 0; r < 16; ++r) {
            int idx = tid * 16 + r;           // 0..4095
            int k   = idx >> 7;
            int n   = idx & 127;
            Bs[k][n] = f32_to_tf32(W[(kk + k) * SUPW + n * 3 + kern]);
        }
        __syncthreads();

        // --- 4 k-steps of 8 ---
        #pragma unroll
        for (int ks = 0; ks < 4; ++ks) {
            int k0 = ks * 8;
            uint32_t af[4][4], bf[4][2];
            #pragma unroll
            for (int mi = 0; mi < 4; ++mi) {
                int rb = warp_m + mi * 16;
                af[mi][0] = As[k0 + qcol][rb + qrow];
                af[mi][1] = As[k0 + qcol][rb + 8 + qrow];
                af[mi][2] = As[k0 + 4 + qcol][rb + qrow];
                af[mi][3] = As[k0 + 4 + qcol][rb + 8 + qrow];
            }
            #pragma unroll
            for (int ni = 0; ni < 4; ++ni) {
                int nb = warp_n + ni * 8;
                bf[ni][0] = Bs[k0 + qcol][nb + qrow];
                bf[ni][1] = Bs[k0 + 4 + qcol][nb + qrow];
            }
            #pragma unroll
            for (int mi = 0; mi < 4; ++mi)
                #pragma unroll
                for (int ni = 0; ni < 4; ++ni)
                    mma_tf32(acc[mi][ni], af[mi][0], af[mi][1], af[mi][2],
                             af[mi][3], bf[ni][0], bf[ni][1]);
        }
        __syncthreads();
    }

    // --- epilogue: c0/c1 at (row, 2*qcol), c2/c3 at (row+8, 2*qcol) ---
    #pragma unroll
    for (int mi = 0; mi < 4; ++mi) {
        int gm_lo = m0 + warp_m + mi * 16 + qrow;
        int gm_hi = gm_lo + 8;
        #pragma unroll
        for (int ni = 0; ni < 4; ++ni) {
            int col = kern * DOUT + warp_n + ni * 8 + 2 * qcol;
            if (gm_lo < n_nodes) {
                float2 v = make_float2(acc[mi][ni][0], acc[mi][ni][1]);
                *reinterpret_cast<float2*>(g_sup + (size_t)gm_lo * SUPW + col) = v;
            }
            if (gm_hi < n_nodes) {
                float2 v = make_float2(acc[mi][ni][2], acc[mi][ni][3]);
                *reinterpret_cast<float2*>(g_sup + (size_t)gm_hi * SUPW + col) = v;
            }
        }
    }
}

// ---------------------------------------------------------------------------
// Kernel 2: gather — ONE WARP PER COL. Loads sup[col] once (3 float4/lane),
// then loops over the col's edge bucket with 1-deep meta prefetch:
//   per edge: 12 FMA + red.global.add.v4.f32 into out[row].
// ---------------------------------------------------------------------------
__device__ __forceinline__ void red_add_f32x4(float* dst, float4 m) {
    asm volatile("red.global.add.v4.f32 [%0], {%1, %2, %3, %4};"
                 :: "l"(dst), "f"(m.x), "f"(m.y), "f"(m.z), "f"(m.w)
                 : "memory");
}

__global__ __launch_bounds__(256)
void gather_kernel(float* __restrict__ out, int n_nodes) {
    int col  = blockIdx.x * (blockDim.x >> 5) + (threadIdx.x >> 5);
    if (col >= n_nodes) return;
    int lane = threadIdx.x & 31;

    int cnt = g_cnt[col];
    if (cnt <= 0) return;
    cnt = min(cnt, BSTRIDE);

    // sup[col]: lane's 4 output cols j = 4*lane..4*lane+3 for each of 3 kernels
    const float4* s = reinterpret_cast<const float4*>(g_sup + (size_t)col * SUPW);
    float4 a = s[lane];          // kernel 0
    float4 b = s[32 + lane];     // kernel 1
    float4 c = s[64 + lane];     // kernel 2

    const float4* mp = g_meta + (size_t)col * BSTRIDE;
    float4 meta = mp[0];                       // prefetch edge 0
    for (int i = 0; i < cnt; ++i) {
        float4 nxt = (i + 1 < cnt) ? mp[i + 1] : meta;   // prefetch next
        int   row = __float_as_int(meta.x);
        float t0 = meta.y, t1 = meta.z, t2 = meta.w;
        float4 m;
        m.x = t0 * a.x + t1 * b.x + t2 * c.x;
        m.y = t0 * a.y + t1 * b.y + t2 * c.y;
        m.z = t0 * a.z + t1 * b.z + t2 * c.z;
        m.w = t0 * a.w + t1 * b.w + t2 * c.w;
        red_add_f32x4(out + (size_t)row * DOUT + lane * 4, m);
        meta = nxt;
    }
}

// ---------------------------------------------------------------------------
// Launch
// ---------------------------------------------------------------------------
extern "C" void kernel_launch(void* const* d_in, const int* in_sizes, int n_in,
                              void* d_out, int out_size) {
    const float* x    = (const float*)d_in[0];      // [N,128] f32
    const float* TT   = (const float*)d_in[1];      // [E,3]   f32
    const float* w    = (const float*)d_in[2];      // [128,128,3] f32
    const float* bias = (const float*)d_in[3];      // [128]   f32
    const int*   eidx = (const int*)d_in[4];        // [2,E]   int32
    float*       out  = (float*)d_out;              // [N,128] f32

    int n_nodes = in_sizes[0] / DIN;     // 50000
    int n_edges = in_sizes[1] / KK;      // 800000

    // 0) out = bias
    {
        int total = n_nodes * (DOUT / 4);
        bias_init_kernel<<<(total + 255) / 256, 256>>>(bias, out, n_nodes);
    }
    // 0b) zero bucket counters (every launch — graph replay safe)
    zero_cnt_kernel<<<(n_nodes + 255) / 256, 256>>>(n_nodes);
    // 0c) fill col buckets with packed {row, t0, t1, t2}
    fill_kernel<<<(n_edges + 255) / 256, 256>>>(TT, eidx, n_edges);
    // 1) support_all = x @ W  (tf32 tensor cores)
    {
        dim3 grid(KK, (n_nodes + GM - 1) / GM);
        gemm_tc_kernel<<<grid, 256>>>(x, w, n_nodes);
    }
    // 2) col-grouped gather + RED scatter (one warp per col)
    {
        int warps_per_block = 256 / 32;
        int blocks = (n_nodes + warps_per_block - 1) / warps_per_block;
        gather_kernel<<<blocks, 256>>>(out, n_nodes);
    }
}

// round 15
// speedup vs baseline: 1.3656x; 1.3547x over previous
#include <cuda_runtime.h>
#include <cuda_bf16.h>
#include <cstdint>

// Problem constants
#define NN      50000
#define EE      800000
#define DIN     128
#define DOUT    128
#define KK      3
#define SUPW    (DOUT * KK)   // 384 floats per node
#define BSTRIDE 64            // max edges per col bucket (Binomial max ~35)

// Scratch (static device globals — allocation-free)
__device__ __align__(16) float    g_sup[(size_t)NN * SUPW];     // 76.8 MB
__device__ int                    g_cnt[NN];                    // per-col counts
__device__ __align__(16) float4   g_meta[(size_t)NN * BSTRIDE]; // 51.2 MB
__device__ __align__(16) uint32_t g_xt[(size_t)NN * DIN];       // X as tf32 bits
__device__ __align__(16) uint32_t g_wt[KK * DIN * DOUT];        // W transposed tf32

__device__ __forceinline__ uint32_t f32_to_tf32(float f) {
    uint32_t r;
    asm("cvt.rna.tf32.f32 %0, %1;" : "=r"(r) : "f"(f));
    return r;
}

__device__ __forceinline__ uint32_t smem_u32(const void* p) {
    return (uint32_t)__cvta_generic_to_shared(p);
}

#define CP16(dst, src) \
    asm volatile("cp.async.cg.shared.global [%0], [%1], 16;\n" \
                 :: "r"(dst), "l"(src) : "memory")

// ---------------------------------------------------------------------------
// Kernel 0: out[n][j] = bias[j]; also zero bucket counters (fused)
// ---------------------------------------------------------------------------
__global__ void bias_init_kernel(const float* __restrict__ bias,
                                 float* __restrict__ out, int n) {
    int i = blockIdx.x * blockDim.x + threadIdx.x;
    int total = n * (DOUT / 4);
    if (i < total) {
        const float4* b4 = reinterpret_cast<const float4*>(bias);
        reinterpret_cast<float4*>(out)[i] = b4[i & (DOUT / 4 - 1)];
    }
    if (i < n) g_cnt[i] = 0;
}

// ---------------------------------------------------------------------------
// Kernel 0a: X -> tf32 bits (rna rounding), vectorized
// ---------------------------------------------------------------------------
__global__ void xt_kernel(const float* __restrict__ X, int total4) {
    int i = blockIdx.x * blockDim.x + threadIdx.x;
    if (i < total4) {
        float4 v = reinterpret_cast<const float4*>(X)[i];
        uint4 o;
        o.x = f32_to_tf32(v.x); o.y = f32_to_tf32(v.y);
        o.z = f32_to_tf32(v.z); o.w = f32_to_tf32(v.w);
        reinterpret_cast<uint4*>(g_xt)[i] = o;
    }
}

// ---------------------------------------------------------------------------
// Kernel 0w: W[k][n][kern] -> g_wt[kern][k][n] as tf32 bits
// ---------------------------------------------------------------------------
__global__ void wt_kernel(const float* __restrict__ W) {
    int i = blockIdx.x * blockDim.x + threadIdx.x;
    if (i < KK * DIN * DOUT) {
        int kern = i / (DIN * DOUT);
        int rem  = i % (DIN * DOUT);
        int k    = rem / DOUT;
        int n    = rem % DOUT;
        g_wt[i] = f32_to_tf32(W[k * SUPW + n * 3 + kern]);
    }
}

// ---------------------------------------------------------------------------
// Kernel 0c: bucket fill — per edge, append {row, t0, t1, t2} to col bucket.
// edge_idx is int32 [2,E] (JAX x64-disabled coerces the requested int64).
// ---------------------------------------------------------------------------
__global__ __launch_bounds__(256)
void fill_kernel(const float* __restrict__ TT,
                 const int* __restrict__ eidx, int n_edges) {
    int e = blockIdx.x * blockDim.x + threadIdx.x;
    if (e >= n_edges) return;
    int row = eidx[e];
    int col = eidx[n_edges + e];
    float t0 = TT[e * 3 + 0];
    float t1 = TT[e * 3 + 1];
    float t2 = TT[e * 3 + 2];
    int pos = atomicAdd(&g_cnt[col], 1);
    if (pos < BSTRIDE)
        g_meta[(size_t)col * BSTRIDE + pos] =
            make_float4(__int_as_float(row), t0, t1, t2);
}

// ---------------------------------------------------------------------------
// Kernel 1: tf32 tensor-core GEMM, cp.async double-buffered.
//   g_sup[:, kern*128 + n] = x @ W[:,:,kern]
//   Tile M=128 x N=128, BK=16 x 2 stages. Warp grid 2m x 4n, warp tile 64x32.
//   As[m][k] stride 20 (20*qrow+qcol covers all banks);
//   Bs[k][n] stride 136 (8*qcol+qrow covers all banks).
// ---------------------------------------------------------------------------
#define GM   128
#define BK2  16
#define NITER (DIN / BK2)     // 8
#define ASTR 20
#define BSTR 136

__device__ __forceinline__ void mma_tf32(float c[4], uint32_t a0, uint32_t a1,
                                         uint32_t a2, uint32_t a3,
                                         uint32_t b0, uint32_t b1) {
    asm volatile(
        "mma.sync.aligned.m16n8k8.row.col.f32.tf32.tf32.f32 "
        "{%0,%1,%2,%3}, {%4,%5,%6,%7}, {%8,%9}, {%0,%1,%2,%3};"
        : "+f"(c[0]), "+f"(c[1]), "+f"(c[2]), "+f"(c[3])
        : "r"(a0), "r"(a1), "r"(a2), "r"(a3), "r"(b0), "r"(b1));
}

__global__ __launch_bounds__(256)
void gemm_tc_kernel(int n_nodes) {
    __shared__ uint32_t As[2][GM][ASTR];    // [stage][m][k]
    __shared__ uint32_t Bs[2][BK2][BSTR];   // [stage][k][n]

    const int kern = blockIdx.x;              // 0..2
    const int m0   = blockIdx.y * GM;
    const int tid  = threadIdx.x;
    const int wid  = tid >> 5;
    const int lane = tid & 31;
    const int qrow = lane >> 2;               // 0..7
    const int qcol = lane & 3;                // 0..3
    const int warp_m = (wid & 1) * 64;
    const int warp_n = (wid >> 1) * 32;

    const uint32_t* wt = g_wt + kern * (DIN * DOUT);

    float acc[4][4][4];
    #pragma unroll
    for (int mi = 0; mi < 4; ++mi)
        #pragma unroll
        for (int ni = 0; ni < 4; ++ni)
            #pragma unroll
            for (int f = 0; f < 4; ++f) acc[mi][ni][f] = 0.0f;

    // stage issue: A = 512 16B chunks (m = c>>2, cc = c&3),
    //              B = 512 16B chunks (k = c>>5, nc = c&31); 2 each per thread
    auto issue = [&](int it) {
        if (it < NITER) {
            int st = it & 1;
            int kk = it * BK2;
            #pragma unroll
            for (int j = 0; j < 2; ++j) {
                int c = tid + j * 256;
                int m  = c >> 2, cc = c & 3;
                if (m0 + m < n_nodes) {
                    uint32_t d = smem_u32(&As[st][m][cc * 4]);
                    CP16(d, g_xt + (size_t)(m0 + m) * DIN + kk + cc * 4);
                }
                int k  = c >> 5, nc = c & 31;
                uint32_t d2 = smem_u32(&Bs[st][k][nc * 4]);
                CP16(d2, wt + (kk + k) * DOUT + nc * 4);
            }
        }
        asm volatile("cp.async.commit_group;\n" ::: "memory");
    };

    issue(0);
    issue(1);

    for (int it = 0; it < NITER; ++it) {
        int st = it & 1;
        asm volatile("cp.async.wait_group 1;\n" ::: "memory");
        __syncthreads();

        #pragma unroll
        for (int ks = 0; ks < 2; ++ks) {
            int k0 = ks * 8;
            uint32_t af[4][4], bf[4][2];
            #pragma unroll
            for (int mi = 0; mi < 4; ++mi) {
                int rb = warp_m + mi * 16;
                af[mi][0] = As[st][rb + qrow][k0 + qcol];
                af[mi][1] = As[st][rb + 8 + qrow][k0 + qcol];
                af[mi][2] = As[st][rb + qrow][k0 + 4 + qcol];
                af[mi][3] = As[st][rb + 8 + qrow][k0 + 4 + qcol];
            }
            #pragma unroll
            for (int ni = 0; ni < 4; ++ni) {
                int nb = warp_n + ni * 8;
                bf[ni][0] = Bs[st][k0 + qcol][nb + qrow];
                bf[ni][1] = Bs[st][k0 + 4 + qcol][nb + qrow];
            }
            #pragma unroll
            for (int mi = 0; mi < 4; ++mi)
                #pragma unroll
                for (int ni = 0; ni < 4; ++ni)
                    mma_tf32(acc[mi][ni], af[mi][0], af[mi][1], af[mi][2],
                             af[mi][3], bf[ni][0], bf[ni][1]);
        }
        __syncthreads();
        issue(it + 2);
    }

    // epilogue: c0/c1 at (row, 2*qcol), c2/c3 at (row+8, 2*qcol)
    #pragma unroll
    for (int mi = 0; mi < 4; ++mi) {
        int gm_lo = m0 + warp_m + mi * 16 + qrow;
        int gm_hi = gm_lo + 8;
        #pragma unroll
        for (int ni = 0; ni < 4; ++ni) {
            int col = kern * DOUT + warp_n + ni * 8 + 2 * qcol;
            if (gm_lo < n_nodes) {
                float2 v = make_float2(acc[mi][ni][0], acc[mi][ni][1]);
                *reinterpret_cast<float2*>(g_sup + (size_t)gm_lo * SUPW + col) = v;
            }
            if (gm_hi < n_nodes) {
                float2 v = make_float2(acc[mi][ni][2], acc[mi][ni][3]);
                *reinterpret_cast<float2*>(g_sup + (size_t)gm_hi * SUPW + col) = v;
            }
        }
    }
}

// ---------------------------------------------------------------------------
// Kernel 2: gather — ONE WARP PER COL. Loads sup[col] once (3 float4/lane),
// then loops over the col's edge bucket with 1-deep meta prefetch:
//   per edge: 12 FMA + red.global.add.v4.f32 into out[row].
// ---------------------------------------------------------------------------
__device__ __forceinline__ void red_add_f32x4(float* dst, float4 m) {
    asm volatile("red.global.add.v4.f32 [%0], {%1, %2, %3, %4};"
                 :: "l"(dst), "f"(m.x), "f"(m.y), "f"(m.z), "f"(m.w)
                 : "memory");
}

__global__ __launch_bounds__(256)
void gather_kernel(float* __restrict__ out, int n_nodes) {
    int col  = blockIdx.x * (blockDim.x >> 5) + (threadIdx.x >> 5);
    if (col >= n_nodes) return;
    int lane = threadIdx.x & 31;

    int cnt = g_cnt[col];
    if (cnt <= 0) return;
    cnt = min(cnt, BSTRIDE);

    const float4* s = reinterpret_cast<const float4*>(g_sup + (size_t)col * SUPW);
    float4 a = s[lane];          // kernel 0
    float4 b = s[32 + lane];     // kernel 1
    float4 c = s[64 + lane];     // kernel 2

    const float4* mp = g_meta + (size_t)col * BSTRIDE;
    float4 meta = mp[0];
    for (int i = 0; i < cnt; ++i) {
        float4 nxt = (i + 1 < cnt) ? mp[i + 1] : meta;
        int   row = __float_as_int(meta.x);
        float t0 = meta.y, t1 = meta.z, t2 = meta.w;
        float4 m;
        m.x = t0 * a.x + t1 * b.x + t2 * c.x;
        m.y = t0 * a.y + t1 * b.y + t2 * c.y;
        m.z = t0 * a.z + t1 * b.z + t2 * c.z;
        m.w = t0 * a.w + t1 * b.w + t2 * c.w;
        red_add_f32x4(out + (size_t)row * DOUT + lane * 4, m);
        meta = nxt;
    }
}

// ---------------------------------------------------------------------------
// Launch
// ---------------------------------------------------------------------------
extern "C" void kernel_launch(void* const* d_in, const int* in_sizes, int n_in,
                              void* d_out, int out_size) {
    const float* x    = (const float*)d_in[0];      // [N,128] f32
    const float* TT   = (const float*)d_in[1];      // [E,3]   f32
    const float* w    = (const float*)d_in[2];      // [128,128,3] f32
    const float* bias = (const float*)d_in[3];      // [128]   f32
    const int*   eidx = (const int*)d_in[4];        // [2,E]   int32
    float*       out  = (float*)d_out;              // [N,128] f32

    int n_nodes = in_sizes[0] / DIN;     // 50000
    int n_edges = in_sizes[1] / KK;      // 800000

    // 0) out = bias; zero bucket counters
    {
        int total = n_nodes * (DOUT / 4);
        bias_init_kernel<<<(total + 255) / 256, 256>>>(bias, out, n_nodes);
    }
    // 0a) X -> tf32
    {
        int total4 = n_nodes * DIN / 4;
        xt_kernel<<<(total4 + 255) / 256, 256>>>(x, total4);
    }
    // 0w) W transpose + tf32
    {
        int total = KK * DIN * DOUT;
        wt_kernel<<<(total + 255) / 256, 256>>>(w);
    }
    // 0c) fill col buckets with packed {row, t0, t1, t2}
    fill_kernel<<<(n_edges + 255) / 256, 256>>>(TT, eidx, n_edges);
    // 1) support_all = x @ W  (tf32 tensor cores, cp.async double-buffered)
    {
        dim3 grid(KK, (n_nodes + GM - 1) / GM);
        gemm_tc_kernel<<<grid, 256>>>(n_nodes);
    }
    // 2) col-grouped gather + RED scatter (one warp per col)
    {
        int warps_per_block = 256 / 32;
        int blocks = (n_nodes + warps_per_block - 1) / warps_per_block;
        gather_kernel<<<blocks, 256>>>(out, n_nodes);
    }
}

// round 16
// speedup vs baseline: 1.3671x; 1.0011x over previous
#include <cuda_runtime.h>
#include <cuda_bf16.h>
#include <cstdint>

// Problem constants
#define NN      50000
#define EE      800000
#define DIN     128
#define DOUT    128
#define KK      3
#define SUPW    (DOUT * KK)   // 384 floats per node
#define BSTRIDE 64            // max edges per col bucket (Binomial max ~35)

// Scratch (static device globals — allocation-free)
__device__ __align__(16) float    g_sup[(size_t)NN * SUPW];     // 76.8 MB
__device__ int                    g_cnt[NN];                    // per-col counts
__device__ __align__(16) float4   g_meta[(size_t)NN * BSTRIDE]; // 51.2 MB
__device__ __align__(16) uint32_t g_xt[(size_t)NN * DIN];       // X as tf32 bits
__device__ __align__(16) uint32_t g_wt[KK * DIN * DOUT];        // W transposed tf32

__device__ __forceinline__ uint32_t f32_to_tf32(float f) {
    uint32_t r;
    asm("cvt.rna.tf32.f32 %0, %1;" : "=r"(r) : "f"(f));
    return r;
}

__device__ __forceinline__ uint32_t smem_u32(const void* p) {
    return (uint32_t)__cvta_generic_to_shared(p);
}

#define CP16(dst, src) \
    asm volatile("cp.async.cg.shared.global [%0], [%1], 16;\n" \
                 :: "r"(dst), "l"(src) : "memory")

// ---------------------------------------------------------------------------
// Kernel 0: out[n][j] = bias[j]; also zero bucket counters (fused)
// ---------------------------------------------------------------------------
__global__ void bias_init_kernel(const float* __restrict__ bias,
                                 float* __restrict__ out, int n) {
    int i = blockIdx.x * blockDim.x + threadIdx.x;
    int total = n * (DOUT / 4);
    if (i < total) {
        const float4* b4 = reinterpret_cast<const float4*>(bias);
        reinterpret_cast<float4*>(out)[i] = b4[i & (DOUT / 4 - 1)];
    }
    if (i < n) g_cnt[i] = 0;
}

// ---------------------------------------------------------------------------
// Kernel 0a: X -> tf32 bits (rna rounding), vectorized
// ---------------------------------------------------------------------------
__global__ void xt_kernel(const float* __restrict__ X, int total4) {
    int i = blockIdx.x * blockDim.x + threadIdx.x;
    if (i < total4) {
        float4 v = reinterpret_cast<const float4*>(X)[i];
        uint4 o;
        o.x = f32_to_tf32(v.x); o.y = f32_to_tf32(v.y);
        o.z = f32_to_tf32(v.z); o.w = f32_to_tf32(v.w);
        reinterpret_cast<uint4*>(g_xt)[i] = o;
    }
}

// ---------------------------------------------------------------------------
// Kernel 0w: W[k][n][kern] -> g_wt[kern][k][n] as tf32 bits
// ---------------------------------------------------------------------------
__global__ void wt_kernel(const float* __restrict__ W) {
    int i = blockIdx.x * blockDim.x + threadIdx.x;
    if (i < KK * DIN * DOUT) {
        int kern = i / (DIN * DOUT);
        int rem  = i % (DIN * DOUT);
        int k    = rem / DOUT;
        int n    = rem % DOUT;
        g_wt[i] = f32_to_tf32(W[k * SUPW + n * 3 + kern]);
    }
}

// ---------------------------------------------------------------------------
// Kernel 0c: bucket fill — per edge, append {row, t0, t1, t2} to col bucket.
// edge_idx is int32 [2,E] (JAX x64-disabled coerces the requested int64).
// ---------------------------------------------------------------------------
__global__ __launch_bounds__(256)
void fill_kernel(const float* __restrict__ TT,
                 const int* __restrict__ eidx, int n_edges) {
    int e = blockIdx.x * blockDim.x + threadIdx.x;
    if (e >= n_edges) return;
    int row = eidx[e];
    int col = eidx[n_edges + e];
    float t0 = TT[e * 3 + 0];
    float t1 = TT[e * 3 + 1];
    float t2 = TT[e * 3 + 2];
    int pos = atomicAdd(&g_cnt[col], 1);
    if (pos < BSTRIDE)
        g_meta[(size_t)col * BSTRIDE + pos] =
            make_float4(__int_as_float(row), t0, t1, t2);
}

// ---------------------------------------------------------------------------
// Kernel 1: tf32 tensor-core GEMM, cp.async double-buffered.
//   g_sup[:, kern*128 + n] = x @ W[:,:,kern]
//   Tile M=128 x N=128, BK=16 x 2 stages. Warp grid 2m x 4n, warp tile 64x32.
//   As[m][k] stride 20 (20*qrow+qcol covers all banks);
//   Bs[k][n] stride 136 (8*qcol+qrow covers all banks).
// ---------------------------------------------------------------------------
#define GM   128
#define BK2  16
#define NITER (DIN / BK2)     // 8
#define ASTR 20
#define BSTR 136

__device__ __forceinline__ void mma_tf32(float c[4], uint32_t a0, uint32_t a1,
                                         uint32_t a2, uint32_t a3,
                                         uint32_t b0, uint32_t b1) {
    asm volatile(
        "mma.sync.aligned.m16n8k8.row.col.f32.tf32.tf32.f32 "
        "{%0,%1,%2,%3}, {%4,%5,%6,%7}, {%8,%9}, {%0,%1,%2,%3};"
        : "+f"(c[0]), "+f"(c[1]), "+f"(c[2]), "+f"(c[3])
        : "r"(a0), "r"(a1), "r"(a2), "r"(a3), "r"(b0), "r"(b1));
}

__global__ __launch_bounds__(256)
void gemm_tc_kernel(int n_nodes) {
    __shared__ uint32_t As[2][GM][ASTR];    // [stage][m][k]
    __shared__ uint32_t Bs[2][BK2][BSTR];   // [stage][k][n]

    const int kern = blockIdx.x;              // 0..2
    const int m0   = blockIdx.y * GM;
    const int tid  = threadIdx.x;
    const int wid  = tid >> 5;
    const int lane = tid & 31;
    const int qrow = lane >> 2;               // 0..7
    const int qcol = lane & 3;                // 0..3
    const int warp_m = (wid & 1) * 64;
    const int warp_n = (wid >> 1) * 32;

    const uint32_t* wt = g_wt + kern * (DIN * DOUT);

    float acc[4][4][4];
    #pragma unroll
    for (int mi = 0; mi < 4; ++mi)
        #pragma unroll
        for (int ni = 0; ni < 4; ++ni)
            #pragma unroll
            for (int f = 0; f < 4; ++f) acc[mi][ni][f] = 0.0f;

    // stage issue: A = 512 16B chunks (m = c>>2, cc = c&3),
    //              B = 512 16B chunks (k = c>>5, nc = c&31); 2 each per thread
    auto issue = [&](int it) {
        if (it < NITER) {
            int st = it & 1;
            int kk = it * BK2;
            #pragma unroll
            for (int j = 0; j < 2; ++j) {
                int c = tid + j * 256;
                int m  = c >> 2, cc = c & 3;
                if (m0 + m < n_nodes) {
                    uint32_t d = smem_u32(&As[st][m][cc * 4]);
                    CP16(d, g_xt + (size_t)(m0 + m) * DIN + kk + cc * 4);
                }
                int k  = c >> 5, nc = c & 31;
                uint32_t d2 = smem_u32(&Bs[st][k][nc * 4]);
                CP16(d2, wt + (kk + k) * DOUT + nc * 4);
            }
        }
        asm volatile("cp.async.commit_group;\n" ::: "memory");
    };

    issue(0);
    issue(1);

    for (int it = 0; it < NITER; ++it) {
        int st = it & 1;
        asm volatile("cp.async.wait_group 1;\n" ::: "memory");
        __syncthreads();

        #pragma unroll
        for (int ks = 0; ks < 2; ++ks) {
            int k0 = ks * 8;
            uint32_t af[4][4], bf[4][2];
            #pragma unroll
            for (int mi = 0; mi < 4; ++mi) {
                int rb = warp_m + mi * 16;
                af[mi][0] = As[st][rb + qrow][k0 + qcol];
                af[mi][1] = As[st][rb + 8 + qrow][k0 + qcol];
                af[mi][2] = As[st][rb + qrow][k0 + 4 + qcol];
                af[mi][3] = As[st][rb + 8 + qrow][k0 + 4 + qcol];
            }
            #pragma unroll
            for (int ni = 0; ni < 4; ++ni) {
                int nb = warp_n + ni * 8;
                bf[ni][0] = Bs[st][k0 + qcol][nb + qrow];
                bf[ni][1] = Bs[st][k0 + 4 + qcol][nb + qrow];
            }
            #pragma unroll
            for (int mi = 0; mi < 4; ++mi)
                #pragma unroll
                for (int ni = 0; ni < 4; ++ni)
                    mma_tf32(acc[mi][ni], af[mi][0], af[mi][1], af[mi][2],
                             af[mi][3], bf[ni][0], bf[ni][1]);
        }
        __syncthreads();
        issue(it + 2);
    }

    // epilogue: c0/c1 at (row, 2*qcol), c2/c3 at (row+8, 2*qcol)
    #pragma unroll
    for (int mi = 0; mi < 4; ++mi) {
        int gm_lo = m0 + warp_m + mi * 16 + qrow;
        int gm_hi = gm_lo + 8;
        #pragma unroll
        for (int ni = 0; ni < 4; ++ni) {
            int col = kern * DOUT + warp_n + ni * 8 + 2 * qcol;
            if (gm_lo < n_nodes) {
                float2 v = make_float2(acc[mi][ni][0], acc[mi][ni][1]);
                *reinterpret_cast<float2*>(g_sup + (size_t)gm_lo * SUPW + col) = v;
            }
            if (gm_hi < n_nodes) {
                float2 v = make_float2(acc[mi][ni][2], acc[mi][ni][3]);
                *reinterpret_cast<float2*>(g_sup + (size_t)gm_hi * SUPW + col) = v;
            }
        }
    }
}

// ---------------------------------------------------------------------------
// Kernel 2: gather — ONE WARP PER COL. Loads sup[col] once (3 float4/lane),
// then loops over the col's edge bucket with 1-deep meta prefetch:
//   per edge: 12 FMA + red.global.add.v4.f32 into out[row].
// ---------------------------------------------------------------------------
__device__ __forceinline__ void red_add_f32x4(float* dst, float4 m) {
    asm volatile("red.global.add.v4.f32 [%0], {%1, %2, %3, %4};"
                 :: "l"(dst), "f"(m.x), "f"(m.y), "f"(m.z), "f"(m.w)
                 : "memory");
}

__global__ __launch_bounds__(256)
void gather_kernel(float* __restrict__ out, int n_nodes) {
    int col  = blockIdx.x * (blockDim.x >> 5) + (threadIdx.x >> 5);
    if (col >= n_nodes) return;
    int lane = threadIdx.x & 31;

    int cnt = g_cnt[col];
    if (cnt <= 0) return;
    cnt = min(cnt, BSTRIDE);

    const float4* s = reinterpret_cast<const float4*>(g_sup + (size_t)col * SUPW);
    float4 a = s[lane];          // kernel 0
    float4 b = s[32 + lane];     // kernel 1
    float4 c = s[64 + lane];     // kernel 2

    const float4* mp = g_meta + (size_t)col * BSTRIDE;
    float4 meta = mp[0];
    for (int i = 0; i < cnt; ++i) {
        float4 nxt = (i + 1 < cnt) ? mp[i + 1] : meta;
        int   row = __float_as_int(meta.x);
        float t0 = meta.y, t1 = meta.z, t2 = meta.w;
        float4 m;
        m.x = t0 * a.x + t1 * b.x + t2 * c.x;
        m.y = t0 * a.y + t1 * b.y + t2 * c.y;
        m.z = t0 * a.z + t1 * b.z + t2 * c.z;
        m.w = t0 * a.w + t1 * b.w + t2 * c.w;
        red_add_f32x4(out + (size_t)row * DOUT + lane * 4, m);
        meta = nxt;
    }
}

// ---------------------------------------------------------------------------
// Launch
// ---------------------------------------------------------------------------
extern "C" void kernel_launch(void* const* d_in, const int* in_sizes, int n_in,
                              void* d_out, int out_size) {
    const float* x    = (const float*)d_in[0];      // [N,128] f32
    const float* TT   = (const float*)d_in[1];      // [E,3]   f32
    const float* w    = (const float*)d_in[2];      // [128,128,3] f32
    const float* bias = (const float*)d_in[3];      // [128]   f32
    const int*   eidx = (const int*)d_in[4];        // [2,E]   int32
    float*       out  = (float*)d_out;              // [N,128] f32

    int n_nodes = in_sizes[0] / DIN;     // 50000
    int n_edges = in_sizes[1] / KK;      // 800000

    // 0) out = bias; zero bucket counters
    {
        int total = n_nodes * (DOUT / 4);
        bias_init_kernel<<<(total + 255) / 256, 256>>>(bias, out, n_nodes);
    }
    // 0a) X -> tf32
    {
        int total4 = n_nodes * DIN / 4;
        xt_kernel<<<(total4 + 255) / 256, 256>>>(x, total4);
    }
    // 0w) W transpose + tf32
    {
        int total = KK * DIN * DOUT;
        wt_kernel<<<(total + 255) / 256, 256>>>(w);
    }
    // 0c) fill col buckets with packed {row, t0, t1, t2}
    fill_kernel<<<(n_edges + 255) / 256, 256>>>(TT, eidx, n_edges);
    // 1) support_all = x @ W  (tf32 tensor cores, cp.async double-buffered)
    {
        dim3 grid(KK, (n_nodes + GM - 1) / GM);
        gemm_tc_kernel<<<grid, 256>>>(n_nodes);
    }
    // 2) col-grouped gather + RED scatter (one warp per col)
    {
        int warps_per_block = 256 / 32;
        int blocks = (n_nodes + warps_per_block - 1) / warps_per_block;
        gather_kernel<<<blocks, 256>>>(out, n_nodes);
    }
}

// round 17
// speedup vs baseline: 1.3893x; 1.0163x over previous
#include <cuda_runtime.h>
#include <cuda_bf16.h>
#include <cstdint>

// Problem constants
#define NN      50000
#define EE      800000
#define DIN     128
#define DOUT    128
#define KK      3
#define SUPW    (DOUT * KK)   // 384 floats per node
#define BSTRIDE 64            // max edges per col bucket (Binomial max ~35)

// Scratch (static device globals — allocation-free)
__device__ __align__(16) float    g_sup[(size_t)NN * SUPW];     // 76.8 MB
__device__ int                    g_cnt[NN];                    // per-col counts
__device__ __align__(16) float4   g_meta[(size_t)NN * BSTRIDE]; // 51.2 MB
__device__ __align__(16) uint32_t g_xt[(size_t)NN * DIN];       // X tf32, k-permuted
__device__ __align__(16) uint32_t g_wt[KK * DIN * DOUT];        // W^T tf32, k-permuted

__device__ __forceinline__ uint32_t f32_to_tf32(float f) {
    uint32_t r;
    asm("cvt.rna.tf32.f32 %0, %1;" : "=r"(r) : "f"(f));
    return r;
}

__device__ __forceinline__ uint32_t smem_u32(const void* p) {
    return (uint32_t)__cvta_generic_to_shared(p);
}

#define CP16(dst, src) \
    asm volatile("cp.async.cg.shared.global [%0], [%1], 16;\n" \
                 :: "r"(dst), "l"(src) : "memory")

// k-permutation within each 16-wide block: p(k) = (k&8) | ((k&3)<<1) | ((k>>2)&1)
// => fragment pair (k0+qcol, k0+4+qcol) lands on adjacent words -> LDS.64.

// ---------------------------------------------------------------------------
// Kernel 0 (fused prep):
//   i < n*32   : out[n][j] = bias[j]  (float4 granularity)
//   i < n*8    : g_xt block-permute-convert (one 16-k block per thread)
//   i < 3072   : g_wt row (kern, n, blk): transpose + permute + convert
//   i < n      : g_cnt[i] = 0
// ---------------------------------------------------------------------------
__global__ void prep_kernel(const float* __restrict__ bias,
                            const float* __restrict__ X,
                            const float* __restrict__ W,
                            float* __restrict__ out, int n) {
    int i = blockIdx.x * blockDim.x + threadIdx.x;
    int total4 = n * (DOUT / 4);
    if (i < total4) {
        const float4* b4 = reinterpret_cast<const float4*>(bias);
        reinterpret_cast<float4*>(out)[i] = b4[i & (DOUT / 4 - 1)];
    }
    if (i < n * (DIN / 16)) {
        // one 16-k block: rows n = i>>3, blk = i&7
        const float4* src = reinterpret_cast<const float4*>(X) + i * 4;
        float4 v0 = src[0], v1 = src[1], v2 = src[2], v3 = src[3];
        uint4 o0, o1, o2, o3;
        o0.x = f32_to_tf32(v0.x); o0.y = f32_to_tf32(v1.x);
        o0.z = f32_to_tf32(v0.y); o0.w = f32_to_tf32(v1.y);
        o1.x = f32_to_tf32(v0.z); o1.y = f32_to_tf32(v1.z);
        o1.z = f32_to_tf32(v0.w); o1.w = f32_to_tf32(v1.w);
        o2.x = f32_to_tf32(v2.x); o2.y = f32_to_tf32(v3.x);
        o2.z = f32_to_tf32(v2.y); o2.w = f32_to_tf32(v3.y);
        o3.x = f32_to_tf32(v2.z); o3.y = f32_to_tf32(v3.z);
        o3.z = f32_to_tf32(v2.w); o3.w = f32_to_tf32(v3.w);
        uint4* dst = reinterpret_cast<uint4*>(g_xt) + i * 4;
        dst[0] = o0; dst[1] = o1; dst[2] = o2; dst[3] = o3;
    }
    if (i < KK * DOUT * (DIN / 16)) {
        // g_wt[kern][nn][blk*16 + p(klocal)] = tf32(W[k][nn][kern])
        int kern = i / (DOUT * 8);
        int rem  = i % (DOUT * 8);
        int nn   = rem >> 3;
        int blk  = rem & 7;
        #pragma unroll
        for (int kl = 0; kl < 16; ++kl) {
            int k = blk * 16 + kl;
            int p = (kl & 8) | ((kl & 3) << 1) | ((kl >> 2) & 1);
            g_wt[kern * (DIN * DOUT) + nn * DIN + blk * 16 + p] =
                f32_to_tf32(W[k * SUPW + nn * 3 + kern]);
        }
    }
    if (i < n) g_cnt[i] = 0;
}

// ---------------------------------------------------------------------------
// Kernel 0c: bucket fill — 4 edges per thread, batched loads (MLP=4).
// edge_idx is int32 [2,E] (JAX x64-disabled coerces the requested int64).
// ---------------------------------------------------------------------------
__global__ __launch_bounds__(256)
void fill_kernel(const float* __restrict__ TT,
                 const int* __restrict__ eidx, int n_edges) {
    int i = blockIdx.x * blockDim.x + threadIdx.x;
    int base = i * 4;
    if (base >= n_edges) return;

    if (base + 4 <= n_edges) {
        int4 rows = reinterpret_cast<const int4*>(eidx)[i];
        int4 cols = reinterpret_cast<const int4*>(eidx + n_edges)[i];
        float4 ta = reinterpret_cast<const float4*>(TT)[i * 3 + 0];
        float4 tb = reinterpret_cast<const float4*>(TT)[i * 3 + 1];
        float4 tc = reinterpret_cast<const float4*>(TT)[i * 3 + 2];

        int p0 = atomicAdd(&g_cnt[cols.x], 1);
        int p1 = atomicAdd(&g_cnt[cols.y], 1);
        int p2 = atomicAdd(&g_cnt[cols.z], 1);
        int p3 = atomicAdd(&g_cnt[cols.w], 1);

        if (p0 < BSTRIDE)
            g_meta[(size_t)cols.x * BSTRIDE + p0] =
                make_float4(__int_as_float(rows.x), ta.x, ta.y, ta.z);
        if (p1 < BSTRIDE)
            g_meta[(size_t)cols.y * BSTRIDE + p1] =
                make_float4(__int_as_float(rows.y), ta.w, tb.x, tb.y);
        if (p2 < BSTRIDE)
            g_meta[(size_t)cols.z * BSTRIDE + p2] =
                make_float4(__int_as_float(rows.z), tb.z, tb.w, tc.x);
        if (p3 < BSTRIDE)
            g_meta[(size_t)cols.w * BSTRIDE + p3] =
                make_float4(__int_as_float(rows.w), tc.y, tc.z, tc.w);
    } else {
        for (int e = base; e < n_edges; ++e) {
            int row = eidx[e];
            int col = eidx[n_edges + e];
            float t0 = TT[e * 3 + 0], t1 = TT[e * 3 + 1], t2 = TT[e * 3 + 2];
            int pos = atomicAdd(&g_cnt[col], 1);
            if (pos < BSTRIDE)
                g_meta[(size_t)col * BSTRIDE + pos] =
                    make_float4(__int_as_float(row), t0, t1, t2);
        }
    }
}

// ---------------------------------------------------------------------------
// Kernel 1: tf32 tensor-core GEMM, cp.async double-buffered, LDS.64 fragments.
//   g_sup[:, kern*128 + n] = x @ W[:,:,kern]
//   Tile M=128 x N=128, BK=16 x 2 stages. Warp grid 2m x 4n, warp tile 64x32.
//   As[m][k-perm] stride 24 (conflict-free 64b), Bs[n][k-perm] stride 20.
// ---------------------------------------------------------------------------
#define GM   128
#define BK2  16
#define NITER (DIN / BK2)     // 8
#define ASTR 24
#define BSTR2 20

__device__ __forceinline__ void mma_tf32(float c[4], uint32_t a0, uint32_t a1,
                                         uint32_t a2, uint32_t a3,
                                         uint32_t b0, uint32_t b1) {
    asm volatile(
        "mma.sync.aligned.m16n8k8.row.col.f32.tf32.tf32.f32 "
        "{%0,%1,%2,%3}, {%4,%5,%6,%7}, {%8,%9}, {%0,%1,%2,%3};"
        : "+f"(c[0]), "+f"(c[1]), "+f"(c[2]), "+f"(c[3])
        : "r"(a0), "r"(a1), "r"(a2), "r"(a3), "r"(b0), "r"(b1));
}

__global__ __launch_bounds__(256, 2)
void gemm_tc_kernel(int n_nodes) {
    __shared__ uint32_t As[2][GM][ASTR];     // [stage][m][k-perm]   24.6 KB
    __shared__ uint32_t Bs[2][DOUT][BSTR2];  // [stage][n][k-perm]   20.5 KB

    const int kern = blockIdx.x;              // 0..2
    const int m0   = blockIdx.y * GM;
    const int tid  = threadIdx.x;
    const int wid  = tid >> 5;
    const int lane = tid & 31;
    const int qrow = lane >> 2;               // 0..7
    const int qcol = lane & 3;                // 0..3
    const int warp_m = (wid & 1) * 64;
    const int warp_n = (wid >> 1) * 32;

    const uint32_t* wt = g_wt + kern * (DIN * DOUT);

    float acc[4][4][4];
    #pragma unroll
    for (int mi = 0; mi < 4; ++mi)
        #pragma unroll
        for (int ni = 0; ni < 4; ++ni)
            #pragma unroll
            for (int f = 0; f < 4; ++f) acc[mi][ni][f] = 0.0f;

    // stage issue: A and B are both 128 rows x 16 words = 512 16B chunks each
    auto issue = [&](int it) {
        if (it < NITER) {
            int st = it & 1;
            #pragma unroll
            for (int j = 0; j < 2; ++j) {
                int c  = tid + j * 256;
                int r  = c >> 2, cc = c & 3;
                if (m0 + r < n_nodes) {
                    uint32_t d = smem_u32(&As[st][r][cc * 4]);
                    CP16(d, g_xt + (size_t)(m0 + r) * DIN + it * 16 + cc * 4);
                }
                uint32_t d2 = smem_u32(&Bs[st][r][cc * 4]);
                CP16(d2, wt + r * DIN + it * 16 + cc * 4);
            }
        }
        asm volatile("cp.async.commit_group;\n" ::: "memory");
    };

    issue(0);
    issue(1);

    for (int it = 0; it < NITER; ++it) {
        int st = it & 1;
        asm volatile("cp.async.wait_group 1;\n" ::: "memory");
        __syncthreads();

        #pragma unroll
        for (int ks = 0; ks < 2; ++ks) {
            uint32_t af[4][4], bf[4][2];
            #pragma unroll
            for (int mi = 0; mi < 4; ++mi) {
                int rb = warp_m + mi * 16;
                uint2 lo = *reinterpret_cast<const uint2*>(
                    &As[st][rb + qrow][ks * 8 + qcol * 2]);
                uint2 hi = *reinterpret_cast<const uint2*>(
                    &As[st][rb + 8 + qrow][ks * 8 + qcol * 2]);
                af[mi][0] = lo.x;  // (m, k=qcol)
                af[mi][1] = hi.x;  // (m+8, k=qcol)
                af[mi][2] = lo.y;  // (m, k=qcol+4)
                af[mi][3] = hi.y;  // (m+8, k=qcol+4)
            }
            #pragma unroll
            for (int ni = 0; ni < 4; ++ni) {
                int nb = warp_n + ni * 8;
                uint2 bb = *reinterpret_cast<const uint2*>(
                    &Bs[st][nb + qrow][ks * 8 + qcol * 2]);
                bf[ni][0] = bb.x;
                bf[ni][1] = bb.y;
            }
            #pragma unroll
            for (int mi = 0; mi < 4; ++mi)
                #pragma unroll
                for (int ni = 0; ni < 4; ++ni)
                    mma_tf32(acc[mi][ni], af[mi][0], af[mi][1], af[mi][2],
                             af[mi][3], bf[ni][0], bf[ni][1]);
        }
        __syncthreads();
        issue(it + 2);
    }

    // epilogue: c0/c1 at (row, 2*qcol), c2/c3 at (row+8, 2*qcol)
    #pragma unroll
    for (int mi = 0; mi < 4; ++mi) {
        int gm_lo = m0 + warp_m + mi * 16 + qrow;
        int gm_hi = gm_lo + 8;
        #pragma unroll
        for (int ni = 0; ni < 4; ++ni) {
            int col = kern * DOUT + warp_n + ni * 8 + 2 * qcol;
            if (gm_lo < n_nodes) {
                float2 v = make_float2(acc[mi][ni][0], acc[mi][ni][1]);
                *reinterpret_cast<float2*>(g_sup + (size_t)gm_lo * SUPW + col) = v;
            }
            if (gm_hi < n_nodes) {
                float2 v = make_float2(acc[mi][ni][2], acc[mi][ni][3]);
                *reinterpret_cast<float2*>(g_sup + (size_t)gm_hi * SUPW + col) = v;
            }
        }
    }
}

// ---------------------------------------------------------------------------
// Kernel 2: gather — ONE WARP PER COL. Loads sup[col] once (3 float4/lane),
// then loops over the col's edge bucket with 1-deep meta prefetch:
//   per edge: 12 FMA + red.global.add.v4.f32 into out[row].
// ---------------------------------------------------------------------------
__device__ __forceinline__ void red_add_f32x4(float* dst, float4 m) {
    asm volatile("red.global.add.v4.f32 [%0], {%1, %2, %3, %4};"
                 :: "l"(dst), "f"(m.x), "f"(m.y), "f"(m.z), "f"(m.w)
                 : "memory");
}

__global__ __launch_bounds__(256)
void gather_kernel(float* __restrict__ out, int n_nodes) {
    int col  = blockIdx.x * (blockDim.x >> 5) + (threadIdx.x >> 5);
    if (col >= n_nodes) return;
    int lane = threadIdx.x & 31;

    int cnt = g_cnt[col];
    if (cnt <= 0) return;
    cnt = min(cnt, BSTRIDE);

    const float4* s = reinterpret_cast<const float4*>(g_sup + (size_t)col * SUPW);
    float4 a = s[lane];          // kernel 0
    float4 b = s[32 + lane];     // kernel 1
    float4 c = s[64 + lane];     // kernel 2

    const float4* mp = g_meta + (size_t)col * BSTRIDE;
    float4 meta = mp[0];
    for (int i = 0; i < cnt; ++i) {
        float4 nxt = (i + 1 < cnt) ? mp[i + 1] : meta;
        int   row = __float_as_int(meta.x);
        float t0 = meta.y, t1 = meta.z, t2 = meta.w;
        float4 m;
        m.x = t0 * a.x + t1 * b.x + t2 * c.x;
        m.y = t0 * a.y + t1 * b.y + t2 * c.y;
        m.z = t0 * a.z + t1 * b.z + t2 * c.z;
        m.w = t0 * a.w + t1 * b.w + t2 * c.w;
        red_add_f32x4(out + (size_t)row * DOUT + lane * 4, m);
        meta = nxt;
    }
}

// ---------------------------------------------------------------------------
// Launch
// ---------------------------------------------------------------------------
extern "C" void kernel_launch(void* const* d_in, const int* in_sizes, int n_in,
                              void* d_out, int out_size) {
    const float* x    = (const float*)d_in[0];      // [N,128] f32
    const float* TT   = (const float*)d_in[1];      // [E,3]   f32
    const float* w    = (const float*)d_in[2];      // [128,128,3] f32
    const float* bias = (const float*)d_in[3];      // [128]   f32
    const int*   eidx = (const int*)d_in[4];        // [2,E]   int32
    float*       out  = (float*)d_out;              // [N,128] f32

    int n_nodes = in_sizes[0] / DIN;     // 50000
    int n_edges = in_sizes[1] / KK;      // 800000

    // 0) fused prep: bias init, cnt zero, X->tf32(perm), W->tf32(perm, transposed)
    {
        int total = n_nodes * (DOUT / 4);
        prep_kernel<<<(total + 255) / 256, 256>>>(bias, x, w, out, n_nodes);
    }
    // 0c) fill col buckets, 4 edges/thread
    {
        int threads_needed = (n_edges + 3) / 4;
        fill_kernel<<<(threads_needed + 255) / 256, 256>>>(TT, eidx, n_edges);
    }
    // 1) support_all = x @ W  (tf32 tensor cores, cp.async + LDS.64 fragments)
    {
        dim3 grid(KK, (n_nodes + GM - 1) / GM);
        gemm_tc_kernel<<<grid, 256>>>(n_nodes);
    }
    // 2) col-grouped gather + RED scatter (one warp per col)
    {
        int warps_per_block = 256 / 32;
        int blocks = (n_nodes + warps_per_block - 1) / warps_per_block;
        gather_kernel<<<blocks, 256>>>(out, n_nodes);
    }
}